// round 7
// baseline (speedup 1.0000x reference)
#include <cuda_runtime.h>

// ---------------------------------------------------------------------------
// NLIF recurrent spiking net — persistent kernel.
// Round 7: packed fma.rn.f32x2 math (halves the FFMA issue floor), hot-spin
// poll (no nanosleep), warp-0 constants moved to SMEM to dodge spills.
// ---------------------------------------------------------------------------

#define NN 2048
#define TT 2048
#define G  147           // CTAs, 1 per SM (all co-resident on 148 SMs)
#define CPT 14           // columns per CTA (147*14 = 2058 >= 2048)
#define NTHREADS 256
#define NWARPS 8
#define CSTRF 4096       // floats per column slab: 2048 rows x (ws,wf)

// smem: weights + reduction scratch + per-column constants
#define SMEM_BYTES ((CPT * CSTRF + CPT * NWARPS + CPT * 8) * 4)

// persistent device state (no allocations allowed)
__device__ __align__(16) float2 g_state[2][NN];   // (s, s_fast), double-buffered
__device__ unsigned g_cnt[TT + 2];                // per-step counters + epoch slot
__device__ float g_part[TT * G * 2];              // per-CTA readout partials

union V4 { float4 f; ulonglong2 u; };

__device__ __forceinline__ unsigned ld_relaxed_u32(const unsigned* p) {
    unsigned v;
    asm volatile("ld.relaxed.gpu.global.u32 %0, [%1];" : "=r"(v) : "l"(p));
    return v;
}
__device__ __forceinline__ unsigned ld_acquire_u32(const unsigned* p) {
    unsigned v;
    asm volatile("ld.acquire.gpu.global.u32 %0, [%1];" : "=r"(v) : "l"(p));
    return v;
}
__device__ __forceinline__ void red_release_add(unsigned* p, unsigned v) {
    asm volatile("red.release.gpu.global.add.u32 [%0], %1;" :: "l"(p), "r"(v) : "memory");
}
// packed 2-wide fp32 fma: d = a*b + c elementwise on (lo,hi)
__device__ __forceinline__ unsigned long long fma2(unsigned long long a,
                                                   unsigned long long b,
                                                   unsigned long long c) {
    unsigned long long d;
    asm("fma.rn.f32x2 %0, %1, %2, %3;" : "=l"(d) : "l"(a), "l"(b), "l"(c));
    return d;
}
__device__ __forceinline__ float unpk_sum(unsigned long long v) {
    float lo, hi;
    asm("mov.b64 {%0, %1}, %2;" : "=f"(lo), "=f"(hi) : "l"(v));
    return lo + hi;
}

__global__ void __launch_bounds__(NTHREADS, 1)
nlif_kernel(const float* __restrict__ x_in,    // [T][2]
            const float* __restrict__ W_syn,   // [N][N]
            const float* __restrict__ W_fast,  // [N][N]
            const float* __restrict__ W_in,    // [2][N]
            const float* __restrict__ I_o,     // [N]
            const float* __restrict__ O,       // [2][N]
            float* __restrict__ out_spikes,    // [T][N]
            float* __restrict__ out_vs)        // [T][N]
{
    extern __shared__ float smem[];
    float* Wc  = smem;                            // [CPT][CSTRF]
    float* red = smem + CPT * CSTRF;              // [CPT][NWARPS]
    float* cst = red + CPT * NWARPS;              // [CPT][8]: wi0,wi1,io,o0,o1

    const int tid  = threadIdx.x;
    const int warp = tid >> 5;
    const int lane = tid & 31;
    const int b    = blockIdx.x;
    const int j0   = b * CPT;

    // epoch base (all counters == R*G at launch start; slot TT+1 bumped at end)
    const unsigned base = ld_relaxed_u32(&g_cnt[TT + 1]);
    const unsigned tgt0 = base + (unsigned)G;

    // ---- stage weight columns into SMEM, interleaved (ws,wf) per row ----
    for (int i = warp; i < NN; i += NWARPS) {
        if (lane < CPT) {
            const int jj = j0 + lane;
            float ws = 0.f, wf = 0.f;
            if (jj < NN) {
                ws = W_syn[(size_t)i * NN + jj];
                wf = W_fast[(size_t)i * NN + jj];
                if (i == jj) ws = 0.f;              // self-recurrence mask
            }
            const int p = i >> 1, r = i & 1;
            Wc[lane * CSTRF + p * 4 + r * 2 + 0] = ws;
            Wc[lane * CSTRF + p * 4 + r * 2 + 1] = wf;
        }
    }
    __syncthreads();

    // ---- pull k=1,2,3 weight chunks into registers as packed pairs ----
    ulonglong2 wr[CPT][3];
    #pragma unroll
    for (int c = 0; c < CPT; c++) {
        #pragma unroll
        for (int kk = 0; kk < 3; kk++) {
            const int p = (kk + 1) * NTHREADS + tid;
            V4 w; w.f = *reinterpret_cast<const float4*>(&Wc[c * CSTRF + p * 4]);
            wr[c][kk] = w.u;
        }
    }

    // ---- per-column persistent state: v,s in warp-0 registers; constants in SMEM ----
    const int j = j0 + lane;
    const bool active = (warp == 0) && (lane < CPT) && (j < NN);
    float v = 0.f, s = 0.f;
    if (active) {
        cst[lane * 8 + 0] = W_in[j];
        cst[lane * 8 + 1] = W_in[NN + j];
        cst[lane * 8 + 2] = I_o[j];
        cst[lane * 8 + 3] = O[j];
        cst[lane * 8 + 4] = O[NN + j];
        __stcg(&g_state[0][j], make_float2(0.f, 0.f));   // t=0 reads parity-0 zeros
    }
    if (warp == 0 && lane == 0) red_release_add(&g_cnt[0], 1u);  // initial publish

    for (int t = 0; t < TT; t++) {
        const int rb = t & 1;
        const int wb = rb ^ 1;

        float x0 = 0.f, x1 = 0.f;
        if (warp == 0) {
            x0 = __ldg(&x_in[2 * t]);            // prefetch input before the wait
            x1 = __ldg(&x_in[2 * t + 1]);
            const unsigned* cp = &g_cnt[t];
            unsigned f = ld_relaxed_u32(cp);
            while ((int)(f - tgt0) < 0) {        // hot spin (one L2 line, 147 pollers)
                f = ld_relaxed_u32(cp);
            }
            (void)ld_acquire_u32(cp);            // acquire: orders state loads below
        }
        __syncthreads();

        // ---- load state: 4 coalesced float4 (rows 2p, 2p+1 per float4) ----
        const float2* srow = g_state[rb];
        V4 st[4];
        #pragma unroll
        for (int k = 0; k < 4; k++) {
            const int p = k * NTHREADS + tid;
            st[k].f = __ldcg(reinterpret_cast<const float4*>(&srow[2 * p]));
        }

        // ---- dot products with packed f32x2 FMAs ----
        float acc[CPT];
        #pragma unroll
        for (int c = 0; c < CPT; c++) {
            V4 w0; w0.f = *reinterpret_cast<const float4*>(&Wc[c * CSTRF + tid * 4]);
            unsigned long long A = fma2(st[0].u.x, w0.u.x, 0ull);
            A = fma2(st[0].u.y, w0.u.y, A);
            #pragma unroll
            for (int kk = 0; kk < 3; kk++) {
                A = fma2(st[kk + 1].u.x, wr[c][kk].x, A);
                A = fma2(st[kk + 1].u.y, wr[c][kk].y, A);
            }
            acc[c] = unpk_sum(A);
        }

        // ---- intra-warp tree reduce, stash per-warp partials ----
        #pragma unroll
        for (int c = 0; c < CPT; c++) {
            float x = acc[c];
            x += __shfl_down_sync(0xffffffffu, x, 16);
            x += __shfl_down_sync(0xffffffffu, x, 8);
            x += __shfl_down_sync(0xffffffffu, x, 4);
            x += __shfl_down_sync(0xffffffffu, x, 2);
            x += __shfl_down_sync(0xffffffffu, x, 1);
            if (lane == 0) red[c * NWARPS + warp] = x;
        }
        __syncthreads();

        if (warp == 0) {
            float r0 = 0.f, r1 = 0.f;
            float s_new = 0.f, gd = 0.f, spk = 0.f, v_new = 0.f, o1c = 0.f;
            if (active) {
                const float4 p0 = *reinterpret_cast<const float4*>(&red[lane * NWARPS]);
                const float4 p1 = *reinterpret_cast<const float4*>(&red[lane * NWARPS + 4]);
                const float sum = ((p0.x + p0.y) + (p0.z + p0.w)) +
                                  ((p1.x + p1.y) + (p1.z + p1.w));
                const float4 cA = *reinterpret_cast<const float4*>(&cst[lane * 8]);
                o1c = cst[lane * 8 + 4];

                const float I_tot  = sum + x0 * cA.x + x1 * cA.y + cA.z;
                const float dv     = (I_tot - v) / 10.0f;          // TAU_M
                const float v_next = v + dv;
                const float gating = fminf(fmaxf(v_next, -1.f), 1.f);
                const float dvc    = fminf(fmaxf(dv, -1.f), 1.f);
                gd                 = gating * dvc;
                s_new              = s + (gd - s) / 10.0f;         // TAU_S
                spk                = (v_next >=  1.f) ? 1.f : 0.f;
                const float sn     = (v_next <= -1.f) ? 1.f : 0.f;
                v_new              = (1.f + spk - sn) * v_next;    // matches reference exactly

                v = v_new; s = s_new;
                __stcg(&g_state[wb][j], make_float2(s_new, gd));
                r0 = cA.w * s_new;
            }
            // publish progress FIRST (release orders the state stores above)
            if (lane == 0) red_release_add(&g_cnt[t + 1], 1u);

            // non-critical outputs after the release
            if (active) {
                out_spikes[(size_t)t * NN + j] = spk;
                out_vs[(size_t)t * NN + j]     = v_new;
                r1 = o1c * s_new;
            }
            #pragma unroll
            for (int o = 16; o; o >>= 1) {
                r0 += __shfl_down_sync(0xffffffffu, r0, o);
                r1 += __shfl_down_sync(0xffffffffu, r1, o);
            }
            if (lane == 0) {
                g_part[((size_t)t * G + b) * 2 + 0] = r0;
                g_part[((size_t)t * G + b) * 2 + 1] = r1;
            }
        }
    }

    // bump the epoch slot (one per CTA per replay)
    if (warp == 0 && lane == 0) red_release_add(&g_cnt[TT + 1], 1u);
}

// epilogue: one warp per timestep, coalesced float2 loads + shfl reduce
__global__ void readout_kernel(float* __restrict__ out_ro) {
    const int t    = blockIdx.x * (blockDim.x >> 5) + (threadIdx.x >> 5);
    const int lane = threadIdx.x & 31;
    if (t < TT) {
        const float2* p = reinterpret_cast<const float2*>(&g_part[(size_t)t * G * 2]);
        float a = 0.f, c = 0.f;
        for (int bb = lane; bb < G; bb += 32) {
            const float2 pv = p[bb];
            a += pv.x;
            c += pv.y;
        }
        #pragma unroll
        for (int o = 16; o; o >>= 1) {
            a += __shfl_down_sync(0xffffffffu, a, o);
            c += __shfl_down_sync(0xffffffffu, c, o);
        }
        if (lane == 0) {
            out_ro[2 * t]     = a;
            out_ro[2 * t + 1] = c;
        }
    }
}

extern "C" void kernel_launch(void* const* d_in, const int* in_sizes, int n_in,
                              void* d_out, int out_size) {
    const float* x_in   = (const float*)d_in[0];
    const float* W_syn  = (const float*)d_in[1];
    const float* W_fast = (const float*)d_in[2];
    const float* W_in   = (const float*)d_in[3];
    const float* I_o    = (const float*)d_in[4];
    const float* O      = (const float*)d_in[5];

    float* out        = (float*)d_out;
    float* out_spikes = out;                                // [T][N]
    float* out_ro     = out + (size_t)TT * NN;              // [T][2]
    float* out_vs     = out + (size_t)TT * NN + 2 * TT;     // [T][N]

    cudaFuncSetAttribute(nlif_kernel,
                         cudaFuncAttributeMaxDynamicSharedMemorySize, SMEM_BYTES);

    nlif_kernel<<<G, NTHREADS, SMEM_BYTES>>>(x_in, W_syn, W_fast, W_in, I_o, O,
                                             out_spikes, out_vs);
    // 8 warps per block, one warp per timestep
    readout_kernel<<<TT / 8, NTHREADS>>>(out_ro);
}